// round 7
// baseline (speedup 1.0000x reference)
#include <cuda_runtime.h>
#include <cuda_bf16.h>
#include <math.h>

#define N_NODES 100000
#define N_EDGES 1600000
#define N_GRAPHS 64
#define D 128

// ---------------- scratch (no allocations allowed) ----------------
// Two ping-pong feature buffers in bf16 (uint4 = 8 bf16): layer l reads one,
// writes the other. All feature rows are PRE-SCALED by norm_src except the
// final layer's output (consumed by pooling).
__device__ uint4 g_bufA4[N_NODES * 16];
__device__ uint4 g_bufB4[N_NODES * 16];
__device__ unsigned short g_Wbt[5 * D * D]; // bf16 W transposed: [l][n][k]
__device__ float g_norm_src[N_NODES];
__device__ float g_norm_dst[N_NODES];
__device__ int   g_indeg[N_NODES];
__device__ int   g_outdeg[N_NODES];
__device__ int   g_rowstart[N_NODES];
__device__ int   g_cursor[N_NODES];
__device__ int   g_col[N_EDGES];
__device__ float g_gsum[N_GRAPHS * D];
__device__ int   g_gcnt[N_GRAPHS];
__device__ int   g_ctr;

__device__ __forceinline__ unsigned packbf2(float lo, float hi) {
    __nv_bfloat162 p = __floats2bfloat162_rn(lo, hi);
    return *reinterpret_cast<unsigned*>(&p);
}
__device__ __forceinline__ float2 unpackbf2(unsigned u) {
    __nv_bfloat162 p = *reinterpret_cast<__nv_bfloat162*>(&u);
    return __bfloat1622float2(p);
}

// ---------------- init ----------------
__global__ void k_zero() {
    int i = blockIdx.x * blockDim.x + threadIdx.x;
    int stride = gridDim.x * blockDim.x;
    for (int j = i; j < N_NODES; j += stride) {
        g_indeg[j] = 0; g_outdeg[j] = 0; g_cursor[j] = 0;
    }
    for (int j = i; j < N_GRAPHS * D; j += stride) g_gsum[j] = 0.f;
    if (i < N_GRAPHS) g_gcnt[i] = 0;
    if (i == 0) g_ctr = 0;
}

__global__ __launch_bounds__(256) void k_deg(const int* __restrict__ src, const int* __restrict__ dst) {
    int t = blockIdx.x * blockDim.x + threadIdx.x;
    if (t >= N_EDGES / 4) return;
    int4 s = ((const int4*)src)[t];
    int4 d = ((const int4*)dst)[t];
    atomicAdd(&g_outdeg[s.x], 1); atomicAdd(&g_outdeg[s.y], 1);
    atomicAdd(&g_outdeg[s.z], 1); atomicAdd(&g_outdeg[s.w], 1);
    atomicAdd(&g_indeg[d.x], 1);  atomicAdd(&g_indeg[d.y], 1);
    atomicAdd(&g_indeg[d.z], 1);  atomicAdd(&g_indeg[d.w], 1);
}

// norms + CSR row-start reservation (order-free contiguous regions, no scan)
__global__ void k_norm() {
    int i = blockIdx.x * blockDim.x + threadIdx.x;
    if (i >= N_NODES) return;
    int od = g_outdeg[i], id = g_indeg[i];
    g_norm_src[i] = rsqrtf((float)(od > 1 ? od : 1));
    g_norm_dst[i] = rsqrtf((float)(id > 1 ? id : 1));
    g_rowstart[i] = atomicAdd(&g_ctr, id);
}

// convert input h (fp32) -> bufA (bf16, PRE-SCALED by norm_src). After k_norm.
__global__ __launch_bounds__(256) void k_cvt(const float* __restrict__ h) {
    int i = blockIdx.x * blockDim.x + threadIdx.x;   // one float4 -> one uint2
    if (i >= N_NODES * 32) return;
    float ns = g_norm_src[i >> 5];
    float4 v = ((const float4*)h)[i];
    uint2 o;
    o.x = packbf2(v.x * ns, v.y * ns);
    o.y = packbf2(v.z * ns, v.w * ns);
    ((uint2*)g_bufA4)[i] = o;
}

// convert all 5 weights fp32 [k][n] -> bf16 transposed [n][k]
__global__ __launch_bounds__(256) void k_cvtW(const float* W0, const float* W1,
                                              const float* W2, const float* W3,
                                              const float* W4) {
    int idx = blockIdx.x * blockDim.x + threadIdx.x;
    if (idx >= 5 * D * D) return;
    const float* Wl[5] = {W0, W1, W2, W3, W4};
    int l = idx >> 14, rem = idx & (D * D - 1);
    int n = rem >> 7, k = rem & 127;
    g_Wbt[idx] = __bfloat16_as_ushort(__float2bfloat16_rn(Wl[l][k * D + n]));
}

__global__ __launch_bounds__(256) void k_fill(const int* __restrict__ src, const int* __restrict__ dst) {
    int t = blockIdx.x * blockDim.x + threadIdx.x;
    if (t >= N_EDGES / 4) return;
    int4 s = ((const int4*)src)[t];
    int4 d = ((const int4*)dst)[t];
    int p0 = atomicAdd(&g_cursor[d.x], 1);
    int p1 = atomicAdd(&g_cursor[d.y], 1);
    int p2 = atomicAdd(&g_cursor[d.z], 1);
    int p3 = atomicAdd(&g_cursor[d.w], 1);
    g_col[g_rowstart[d.x] + p0] = s.x;
    g_col[g_rowstart[d.y] + p1] = s.y;
    g_col[g_rowstart[d.z] + p2] = s.z;
    g_col[g_rowstart[d.w] + p3] = s.w;
}

// ---------------- Fused layer: out = (Agg(in) @ W + b) [* norm_src]
// Phase 1 (gather): each warp gather-sums 8 dst rows into smem As (bf16,
//   norm_dst applied). 2 edges/warp-step (16 lanes x uint4 per row), 8-edge
//   unroll = 4 independent col->gather chains for latency hiding.
// Phase 2 (MMA): 64x128x128 bf16 m16n8k16, W cached in smem.
#define BM 64
#define AS_STRIDE 136
#define WS_STRIDE 136
#define WS_ELEMS (D * WS_STRIDE)
#define LAYER_SMEM ((WS_ELEMS + BM * AS_STRIDE) * 2)   // 52224 B

__global__ __launch_bounds__(256, 3) void k_layer(const uint4* __restrict__ in,
                                                  uint4* __restrict__ outbuf,
                                                  const unsigned short* __restrict__ Wbt,
                                                  const float* __restrict__ bias,
                                                  int scale_out) {
    extern __shared__ __align__(16) unsigned short sm16[];
    unsigned short* Ws = sm16;               // [n=128][k stride 136]
    unsigned short* As = sm16 + WS_ELEMS;    // [m=64][k stride 136]
    int tid = threadIdx.x;
    int warp = tid >> 5, lane = tid & 31;
    int row0 = blockIdx.x * BM;

    // W copy (independent of gather; issued first so it overlaps)
    const uint4* Wt4 = (const uint4*)Wbt;    // 2048 uint4
#pragma unroll
    for (int i = 0; i < 8; i++) {
        int f = tid + i * 256;
        int n = f >> 4, k0 = (f & 15) * 8;
        *(uint4*)(Ws + n * WS_STRIDE + k0) = Wt4[f];
    }

    // ---- Phase 1: gather-sum 8 nodes per warp ----
    int half = lane >> 4;            // 0/1: which edge of the pair
    int sub  = lane & 15;            // uint4 index within 256B row

#define ACC8(v) do {                                              \
        float2 f_;                                                \
        f_ = unpackbf2((v).x); a0.x += f_.x; a0.y += f_.y;        \
        f_ = unpackbf2((v).y); a1.x += f_.x; a1.y += f_.y;        \
        f_ = unpackbf2((v).z); a2.x += f_.x; a2.y += f_.y;        \
        f_ = unpackbf2((v).w); a3.x += f_.x; a3.y += f_.y;        \
    } while (0)

    for (int i = 0; i < 8; i++) {
        int node = row0 + warp * 8 + i;
        float2 a0 = {0.f, 0.f}, a1 = {0.f, 0.f}, a2 = {0.f, 0.f}, a3 = {0.f, 0.f};
        float nd = 0.f;
        if (node < N_NODES) {
            nd = g_norm_dst[node];
            const int start = g_rowstart[node];
            const int deg   = g_indeg[node];
            int e = 0;
            for (; e + 8 <= deg; e += 8) {          // 4 independent chains
                int cA = g_col[start + e + half];
                int cB = g_col[start + e + 2 + half];
                int cC = g_col[start + e + 4 + half];
                int cD = g_col[start + e + 6 + half];
                uint4 vA = in[(size_t)cA * 16 + sub];
                uint4 vB = in[(size_t)cB * 16 + sub];
                uint4 vC = in[(size_t)cC * 16 + sub];
                uint4 vD = in[(size_t)cD * 16 + sub];
                ACC8(vA); ACC8(vB); ACC8(vC); ACC8(vD);
            }
            for (; e + 2 <= deg; e += 2) {
                int c = g_col[start + e + half];
                uint4 v = in[(size_t)c * 16 + sub];
                ACC8(v);
            }
            if (e < deg && half == 0) {
                int c = g_col[start + e];
                uint4 v = in[(size_t)c * 16 + sub];
                ACC8(v);
            }
        }
        // combine halves (lane L <-> L^16 hold the same features)
        a0.x += __shfl_xor_sync(0xffffffffu, a0.x, 16);
        a0.y += __shfl_xor_sync(0xffffffffu, a0.y, 16);
        a1.x += __shfl_xor_sync(0xffffffffu, a1.x, 16);
        a1.y += __shfl_xor_sync(0xffffffffu, a1.y, 16);
        a2.x += __shfl_xor_sync(0xffffffffu, a2.x, 16);
        a2.y += __shfl_xor_sync(0xffffffffu, a2.y, 16);
        a3.x += __shfl_xor_sync(0xffffffffu, a3.x, 16);
        a3.y += __shfl_xor_sync(0xffffffffu, a3.y, 16);
        if (half == 0) {
            uint4 o;
            o.x = packbf2(a0.x * nd, a0.y * nd);
            o.y = packbf2(a1.x * nd, a1.y * nd);
            o.z = packbf2(a2.x * nd, a2.y * nd);
            o.w = packbf2(a3.x * nd, a3.y * nd);
            *(uint4*)(As + (warp * 8 + i) * AS_STRIDE + sub * 8) = o;
        }
    }
#undef ACC8
    __syncthreads();

    // ---- Phase 2: MMA ----
    int wm = (warp >> 2) * 32;
    int wn = (warp & 3) * 32;
    int qr = lane >> 2;
    int qc = lane & 3;

    float c[2][4][4];
#pragma unroll
    for (int mt = 0; mt < 2; mt++)
#pragma unroll
        for (int nt = 0; nt < 4; nt++)
#pragma unroll
            for (int j = 0; j < 4; j++) c[mt][nt][j] = 0.f;

#pragma unroll
    for (int ks = 0; ks < 8; ks++) {
        int k0 = ks * 16;
        unsigned a[2][4];
#pragma unroll
        for (int mt = 0; mt < 2; mt++) {
            const unsigned short* base = As + (wm + mt * 16 + qr) * AS_STRIDE + k0 + 2 * qc;
            a[mt][0] = *(const unsigned*)(base);
            a[mt][1] = *(const unsigned*)(base + 8 * AS_STRIDE);
            a[mt][2] = *(const unsigned*)(base + 8);
            a[mt][3] = *(const unsigned*)(base + 8 * AS_STRIDE + 8);
        }
#pragma unroll
        for (int nt = 0; nt < 4; nt++) {
            const unsigned short* bb = Ws + (wn + nt * 8 + qr) * WS_STRIDE + k0 + 2 * qc;
            unsigned b0 = *(const unsigned*)(bb);
            unsigned b1 = *(const unsigned*)(bb + 8);
#pragma unroll
            for (int mt = 0; mt < 2; mt++) {
                asm volatile(
                    "mma.sync.aligned.m16n8k16.row.col.f32.bf16.bf16.f32 "
                    "{%0,%1,%2,%3}, {%4,%5,%6,%7}, {%8,%9}, {%0,%1,%2,%3};"
                    : "+f"(c[mt][nt][0]), "+f"(c[mt][nt][1]),
                      "+f"(c[mt][nt][2]), "+f"(c[mt][nt][3])
                    : "r"(a[mt][0]), "r"(a[mt][1]), "r"(a[mt][2]), "r"(a[mt][3]),
                      "r"(b0), "r"(b1));
            }
        }
    }

    // Epilogue: + bias; optionally pre-scale by norm_src for the next layer.
    unsigned short* outb = (unsigned short*)outbuf;
#pragma unroll
    for (int mt = 0; mt < 2; mt++) {
        int r_lo = row0 + wm + mt * 16 + qr;
        int r_hi = r_lo + 8;
        float s_lo = 1.f, s_hi = 1.f;
        if (scale_out) {
            if (r_lo < N_NODES) s_lo = g_norm_src[r_lo];
            if (r_hi < N_NODES) s_hi = g_norm_src[r_hi];
        }
#pragma unroll
        for (int nt = 0; nt < 4; nt++) {
            int col = wn + nt * 8 + qc * 2;
            float2 bb = *(const float2*)(bias + col);
            if (r_lo < N_NODES)
                *(unsigned*)(outb + (size_t)r_lo * D + col) =
                    packbf2((c[mt][nt][0] + bb.x) * s_lo, (c[mt][nt][1] + bb.y) * s_lo);
            if (r_hi < N_NODES)
                *(unsigned*)(outb + (size_t)r_hi * D + col) =
                    packbf2((c[mt][nt][2] + bb.x) * s_hi, (c[mt][nt][3] + bb.y) * s_hi);
        }
    }
}

// ---------------- mean-pool (graph_ids sorted -> run-length segmented reduce)
#define POOL_NODES 256
__global__ __launch_bounds__(128) void k_pool(const int* __restrict__ gid,
                                              const uint4* __restrict__ inbuf) {
    __shared__ int sg[POOL_NODES];
    int base = blockIdx.x * POOL_NODES;
    int tid = threadIdx.x;   // feature index
    for (int i = tid; i < POOL_NODES; i += 128) {
        int n = base + i;
        sg[i] = (n < N_NODES) ? gid[n] : -1;
    }
    __syncthreads();
    int nn = N_NODES - base; if (nn > POOL_NODES) nn = POOL_NODES;
    const unsigned short* h = (const unsigned short*)inbuf;

    float acc = 0.f;
    int cur = sg[0];
    int run = 0;
    for (int i = 0; i < nn; i++) {
        int g = sg[i];
        if (g != cur) {
            atomicAdd(&g_gsum[cur * D + tid], acc);
            if (tid == 0) atomicAdd(&g_gcnt[cur], run);
            acc = 0.f; run = 0; cur = g;
        }
        acc += __bfloat162float(__ushort_as_bfloat16(h[(size_t)(base + i) * D + tid]));
        run++;
    }
    atomicAdd(&g_gsum[cur * D + tid], acc);
    if (tid == 0) atomicAdd(&g_gcnt[cur], run);
}

// ---------------- head: sigmoid(mean @ fc_w^T + fc_b)
__global__ __launch_bounds__(128) void k_final(const float* __restrict__ fcw,
                                               const float* __restrict__ fcb,
                                               float* __restrict__ out) {
    __shared__ float red[128];
    int g = blockIdx.x;
    int tid = threadIdx.x;
    red[tid] = g_gsum[g * D + tid] * fcw[tid];
    __syncthreads();
#pragma unroll
    for (int s = 64; s > 0; s >>= 1) {
        if (tid < s) red[tid] += red[tid + s];
        __syncthreads();
    }
    if (tid == 0) {
        int c = g_gcnt[g]; if (c < 1) c = 1;
        float x = red[0] / (float)c + fcb[0];
        out[g] = 1.f / (1.f + expf(-x));
    }
}

// ---------------- launch ----------------
extern "C" void kernel_launch(void* const* d_in, const int* in_sizes, int n_in,
                              void* d_out, int out_size) {
    const float* h    = (const float*)d_in[0];
    const int*   src  = (const int*)  d_in[1];
    const int*   dst  = (const int*)  d_in[2];
    const int*   gid  = (const int*)  d_in[3];
    const float* W[5] = {(const float*)d_in[4],  (const float*)d_in[6],
                         (const float*)d_in[8],  (const float*)d_in[10],
                         (const float*)d_in[12]};
    const float* b[5] = {(const float*)d_in[5],  (const float*)d_in[7],
                         (const float*)d_in[9],  (const float*)d_in[11],
                         (const float*)d_in[13]};
    const float* fcw  = (const float*)d_in[14];
    const float* fcb  = (const float*)d_in[15];
    float* out = (float*)d_out;

    cudaFuncSetAttribute(k_layer, cudaFuncAttributeMaxDynamicSharedMemorySize, LAYER_SMEM);

    uint4 *bufA, *bufB;
    unsigned short* Wbt;
    cudaGetSymbolAddress((void**)&bufA, g_bufA4);
    cudaGetSymbolAddress((void**)&bufB, g_bufB4);
    cudaGetSymbolAddress((void**)&Wbt, g_Wbt);

    k_zero<<<256, 256>>>();
    k_deg <<<(N_EDGES / 4 + 255) / 256, 256>>>(src, dst);
    k_norm<<<(N_NODES + 255) / 256, 256>>>();
    k_cvt <<<(N_NODES * 32 + 255) / 256, 256>>>(h);         // needs norm_src
    k_cvtW<<<(5 * D * D + 255) / 256, 256>>>(W[0], W[1], W[2], W[3], W[4]);
    k_fill<<<(N_EDGES / 4 + 255) / 256, 256>>>(src, dst);

    const int layer_blocks = (N_NODES + BM - 1) / BM;       // 1563

    for (int l = 0; l < 5; l++) {
        const uint4* inb = (l & 1) ? bufB : bufA;
        uint4* outb      = (l & 1) ? bufA : bufB;
        k_layer<<<layer_blocks, 256, LAYER_SMEM>>>(inb, outb, Wbt + l * D * D,
                                                   b[l], l < 4 ? 1 : 0);
    }

    // layer 4 (l=4, even) wrote bufB
    k_pool <<<(N_NODES + POOL_NODES - 1) / POOL_NODES, 128>>>(gid, bufB);
    k_final<<<N_GRAPHS, 128>>>(fcw, fcb, out);
}

// round 8
// speedup vs baseline: 1.1066x; 1.1066x over previous
#include <cuda_runtime.h>
#include <cuda_bf16.h>
#include <math.h>

#define N_NODES 100000
#define N_EDGES 1600000
#define N_GRAPHS 64
#define D 128

// ---------------- scratch (no allocations allowed) ----------------
__device__ uint4 g_bufA4[N_NODES * 16];   // GEMM output / SpMM input (pre-scaled)
__device__ uint4 g_bufB4[N_NODES * 16];   // SpMM output / GEMM input
__device__ unsigned short g_Wbt[5 * D * D]; // bf16 W transposed: [l][n][k]
__device__ float g_norm_src[N_NODES];
__device__ float g_norm_dst[N_NODES];
__device__ int   g_indeg[N_NODES];
__device__ int   g_outdeg[N_NODES];
__device__ int   g_rowstart[N_NODES];
__device__ int   g_cursor[N_NODES];
__device__ int   g_col[N_EDGES];
__device__ float g_gsum[N_GRAPHS * D];
__device__ int   g_gcnt[N_GRAPHS];
__device__ int   g_ctr;

__device__ __forceinline__ unsigned packbf2(float lo, float hi) {
    __nv_bfloat162 p = __floats2bfloat162_rn(lo, hi);
    return *reinterpret_cast<unsigned*>(&p);
}
__device__ __forceinline__ float2 unpackbf2(unsigned u) {
    __nv_bfloat162 p = *reinterpret_cast<__nv_bfloat162*>(&u);
    return __bfloat1622float2(p);
}

// ---------------- init ----------------
__global__ void k_zero() {
    int i = blockIdx.x * blockDim.x + threadIdx.x;
    int stride = gridDim.x * blockDim.x;
    for (int j = i; j < N_NODES; j += stride) {
        g_indeg[j] = 0; g_outdeg[j] = 0; g_cursor[j] = 0;
    }
    for (int j = i; j < N_GRAPHS * D; j += stride) g_gsum[j] = 0.f;
    if (i < N_GRAPHS) g_gcnt[i] = 0;
    if (i == 0) g_ctr = 0;
}

__global__ __launch_bounds__(256) void k_deg(const int* __restrict__ src, const int* __restrict__ dst) {
    int t = blockIdx.x * blockDim.x + threadIdx.x;
    if (t >= N_EDGES / 4) return;
    int4 s = ((const int4*)src)[t];
    int4 d = ((const int4*)dst)[t];
    atomicAdd(&g_outdeg[s.x], 1); atomicAdd(&g_outdeg[s.y], 1);
    atomicAdd(&g_outdeg[s.z], 1); atomicAdd(&g_outdeg[s.w], 1);
    atomicAdd(&g_indeg[d.x], 1);  atomicAdd(&g_indeg[d.y], 1);
    atomicAdd(&g_indeg[d.z], 1);  atomicAdd(&g_indeg[d.w], 1);
}

// norms + CSR row-start reservation (order-free contiguous regions, no scan)
__global__ void k_norm() {
    int i = blockIdx.x * blockDim.x + threadIdx.x;
    if (i >= N_NODES) return;
    int od = g_outdeg[i], id = g_indeg[i];
    g_norm_src[i] = rsqrtf((float)(od > 1 ? od : 1));
    g_norm_dst[i] = rsqrtf((float)(id > 1 ? id : 1));
    g_rowstart[i] = atomicAdd(&g_ctr, id);
}

// convert input h (fp32) -> bufA (bf16, PRE-SCALED by norm_src). After k_norm.
__global__ __launch_bounds__(256) void k_cvt(const float* __restrict__ h) {
    int i = blockIdx.x * blockDim.x + threadIdx.x;   // one float4 -> one uint2
    if (i >= N_NODES * 32) return;
    float ns = g_norm_src[i >> 5];
    float4 v = ((const float4*)h)[i];
    uint2 o;
    o.x = packbf2(v.x * ns, v.y * ns);
    o.y = packbf2(v.z * ns, v.w * ns);
    ((uint2*)g_bufA4)[i] = o;
}

// convert all 5 weights fp32 [k][n] -> bf16 transposed [n][k]
__global__ __launch_bounds__(256) void k_cvtW(const float* W0, const float* W1,
                                              const float* W2, const float* W3,
                                              const float* W4) {
    int idx = blockIdx.x * blockDim.x + threadIdx.x;
    if (idx >= 5 * D * D) return;
    const float* Wl[5] = {W0, W1, W2, W3, W4};
    int l = idx >> 14, rem = idx & (D * D - 1);
    int n = rem >> 7, k = rem & 127;
    g_Wbt[idx] = __bfloat16_as_ushort(__float2bfloat16_rn(Wl[l][k * D + n]));
}

__global__ __launch_bounds__(256) void k_fill(const int* __restrict__ src, const int* __restrict__ dst) {
    int t = blockIdx.x * blockDim.x + threadIdx.x;
    if (t >= N_EDGES / 4) return;
    int4 s = ((const int4*)src)[t];
    int4 d = ((const int4*)dst)[t];
    int p0 = atomicAdd(&g_cursor[d.x], 1);
    int p1 = atomicAdd(&g_cursor[d.y], 1);
    int p2 = atomicAdd(&g_cursor[d.z], 1);
    int p3 = atomicAdd(&g_cursor[d.w], 1);
    g_col[g_rowstart[d.x] + p0] = s.x;
    g_col[g_rowstart[d.y] + p1] = s.y;
    g_col[g_rowstart[d.z] + p2] = s.z;
    g_col[g_rowstart[d.w] + p3] = s.w;
}

// ---------------- SpMM (features pre-scaled by norm_src -> pure gather-sum):
// agg[i] = norm_dst[i] * sum_{e in row i} hs[col[e]]
// Warp per dst node, 2 edges per step (16 lanes x uint4 per 256B row),
// 8-edge unroll = 4 independent col->gather chains. High occupancy (no smem).
__global__ __launch_bounds__(256) void k_spmm() {
    int gt = blockIdx.x * blockDim.x + threadIdx.x;
    int node = gt >> 5;
    int lane = gt & 31;
    if (node >= N_NODES) return;
    int half = lane >> 4;            // 0 / 1
    int sub  = lane & 15;            // uint4 index within row

    const uint4* __restrict__ hb = g_bufA4;
    const int start = g_rowstart[node];
    const int deg   = g_indeg[node];

    float2 a0 = {0.f, 0.f}, a1 = {0.f, 0.f}, a2 = {0.f, 0.f}, a3 = {0.f, 0.f};

#define ACC8(v) do {                                              \
        float2 f_;                                                \
        f_ = unpackbf2((v).x); a0.x += f_.x; a0.y += f_.y;        \
        f_ = unpackbf2((v).y); a1.x += f_.x; a1.y += f_.y;        \
        f_ = unpackbf2((v).z); a2.x += f_.x; a2.y += f_.y;        \
        f_ = unpackbf2((v).w); a3.x += f_.x; a3.y += f_.y;        \
    } while (0)

    int e = 0;
    for (; e + 8 <= deg; e += 8) {            // 4 independent chains
        int cA = g_col[start + e + half];
        int cB = g_col[start + e + 2 + half];
        int cC = g_col[start + e + 4 + half];
        int cD = g_col[start + e + 6 + half];
        uint4 vA = hb[(size_t)cA * 16 + sub];
        uint4 vB = hb[(size_t)cB * 16 + sub];
        uint4 vC = hb[(size_t)cC * 16 + sub];
        uint4 vD = hb[(size_t)cD * 16 + sub];
        ACC8(vA); ACC8(vB); ACC8(vC); ACC8(vD);
    }
    for (; e + 2 <= deg; e += 2) {
        int c = g_col[start + e + half];
        uint4 v = hb[(size_t)c * 16 + sub];
        ACC8(v);
    }
    if (e < deg && half == 0) {
        int c = g_col[start + e];
        uint4 v = hb[(size_t)c * 16 + sub];
        ACC8(v);
    }
#undef ACC8

    a0.x += __shfl_xor_sync(0xffffffffu, a0.x, 16);
    a0.y += __shfl_xor_sync(0xffffffffu, a0.y, 16);
    a1.x += __shfl_xor_sync(0xffffffffu, a1.x, 16);
    a1.y += __shfl_xor_sync(0xffffffffu, a1.y, 16);
    a2.x += __shfl_xor_sync(0xffffffffu, a2.x, 16);
    a2.y += __shfl_xor_sync(0xffffffffu, a2.y, 16);
    a3.x += __shfl_xor_sync(0xffffffffu, a3.x, 16);
    a3.y += __shfl_xor_sync(0xffffffffu, a3.y, 16);

    if (half == 0) {
        float nd = g_norm_dst[node];
        uint4 o;
        o.x = packbf2(a0.x * nd, a0.y * nd);
        o.y = packbf2(a1.x * nd, a1.y * nd);
        o.z = packbf2(a2.x * nd, a2.y * nd);
        o.w = packbf2(a3.x * nd, a3.y * nd);
        g_bufB4[(size_t)node * 16 + sub] = o;
    }
}

// ---------------- GEMM (bf16 tensor cores): bufA = (bufB @ W + b) [* norm_src]
// Block tile 128x128xK=128, 256 threads = 8 warps (2M x 4N), warp = 64x32
// (4 m-tiles x 4 n-tiles of m16n8k16). Same fragment mapping as BM=64 version.
#define BM 128
#define AS_STRIDE 136
#define WS_STRIDE 136
#define WS_ELEMS (D * WS_STRIDE)
#define GEMM_SMEM ((WS_ELEMS + BM * AS_STRIDE) * 2)   // 69632 B

__global__ __launch_bounds__(256, 2) void k_gemm(const unsigned short* __restrict__ Wbt,
                                                 const float* __restrict__ bias,
                                                 int scale_out) {
    extern __shared__ __align__(16) unsigned short sm16[];
    unsigned short* Ws = sm16;               // [n=128][k stride 136]
    unsigned short* As = sm16 + WS_ELEMS;    // [m=128][k stride 136]
    int tid = threadIdx.x;
    int row0 = blockIdx.x * BM;

    // W: straight uint4 copy (already bf16 transposed [n][k])
    const uint4* Wt4 = (const uint4*)Wbt;    // 2048 uint4
#pragma unroll
    for (int i = 0; i < 8; i++) {
        int f = tid + i * 256;
        int n = f >> 4, k0 = (f & 15) * 8;
        *(uint4*)(Ws + n * WS_STRIDE + k0) = Wt4[f];
    }
    // A tile (bf16, 128 rows x 256B)
#pragma unroll
    for (int i = 0; i < 8; i++) {
        int f = tid + i * 256;               // 2048 uint4 (16 per row)
        int r = f >> 4, c = f & 15;
        int grow = row0 + r;
        uint4 v = (grow < N_NODES) ? g_bufB4[(size_t)grow * 16 + c]
                                   : make_uint4(0u, 0u, 0u, 0u);
        *(uint4*)(As + r * AS_STRIDE + c * 8) = v;
    }
    __syncthreads();

    int warp = tid >> 5, lane = tid & 31;
    int wm = (warp >> 2) * 64;               // 0 / 64
    int wn = (warp & 3) * 32;                // 0 / 32 / 64 / 96
    int qr = lane >> 2;                      // 0..7
    int qc = lane & 3;                       // 0..3

    float c[4][4][4];
#pragma unroll
    for (int mt = 0; mt < 4; mt++)
#pragma unroll
        for (int nt = 0; nt < 4; nt++)
#pragma unroll
            for (int j = 0; j < 4; j++) c[mt][nt][j] = 0.f;

#pragma unroll
    for (int ks = 0; ks < 8; ks++) {
        int k0 = ks * 16;
        unsigned a[4][4];
#pragma unroll
        for (int mt = 0; mt < 4; mt++) {
            const unsigned short* base = As + (wm + mt * 16 + qr) * AS_STRIDE + k0 + 2 * qc;
            a[mt][0] = *(const unsigned*)(base);
            a[mt][1] = *(const unsigned*)(base + 8 * AS_STRIDE);
            a[mt][2] = *(const unsigned*)(base + 8);
            a[mt][3] = *(const unsigned*)(base + 8 * AS_STRIDE + 8);
        }
#pragma unroll
        for (int nt = 0; nt < 4; nt++) {
            const unsigned short* bb = Ws + (wn + nt * 8 + qr) * WS_STRIDE + k0 + 2 * qc;
            unsigned b0 = *(const unsigned*)(bb);
            unsigned b1 = *(const unsigned*)(bb + 8);
#pragma unroll
            for (int mt = 0; mt < 4; mt++) {
                asm volatile(
                    "mma.sync.aligned.m16n8k16.row.col.f32.bf16.bf16.f32 "
                    "{%0,%1,%2,%3}, {%4,%5,%6,%7}, {%8,%9}, {%0,%1,%2,%3};"
                    : "+f"(c[mt][nt][0]), "+f"(c[mt][nt][1]),
                      "+f"(c[mt][nt][2]), "+f"(c[mt][nt][3])
                    : "r"(a[mt][0]), "r"(a[mt][1]), "r"(a[mt][2]), "r"(a[mt][3]),
                      "r"(b0), "r"(b1));
            }
        }
    }

    // Epilogue: + bias; optionally pre-scale by norm_src for next layer's SpMM.
    unsigned short* outb = (unsigned short*)g_bufA4;
#pragma unroll
    for (int mt = 0; mt < 4; mt++) {
        int r_lo = row0 + wm + mt * 16 + qr;
        int r_hi = r_lo + 8;
        float s_lo = 1.f, s_hi = 1.f;
        if (scale_out) {
            if (r_lo < N_NODES) s_lo = g_norm_src[r_lo];
            if (r_hi < N_NODES) s_hi = g_norm_src[r_hi];
        }
#pragma unroll
        for (int nt = 0; nt < 4; nt++) {
            int col = wn + nt * 8 + qc * 2;
            float2 bb = *(const float2*)(bias + col);
            if (r_lo < N_NODES)
                *(unsigned*)(outb + (size_t)r_lo * D + col) =
                    packbf2((c[mt][nt][0] + bb.x) * s_lo, (c[mt][nt][1] + bb.y) * s_lo);
            if (r_hi < N_NODES)
                *(unsigned*)(outb + (size_t)r_hi * D + col) =
                    packbf2((c[mt][nt][2] + bb.x) * s_hi, (c[mt][nt][3] + bb.y) * s_hi);
        }
    }
}

// ---------------- mean-pool (graph_ids sorted -> run-length segmented reduce)
#define POOL_NODES 256
__global__ __launch_bounds__(128) void k_pool(const int* __restrict__ gid) {
    __shared__ int sg[POOL_NODES];
    int base = blockIdx.x * POOL_NODES;
    int tid = threadIdx.x;   // feature index
    for (int i = tid; i < POOL_NODES; i += 128) {
        int n = base + i;
        sg[i] = (n < N_NODES) ? gid[n] : -1;
    }
    __syncthreads();
    int nn = N_NODES - base; if (nn > POOL_NODES) nn = POOL_NODES;
    const unsigned short* h = (const unsigned short*)g_bufA4;

    float acc = 0.f;
    int cur = sg[0];
    int run = 0;
    for (int i = 0; i < nn; i++) {
        int g = sg[i];
        if (g != cur) {
            atomicAdd(&g_gsum[cur * D + tid], acc);
            if (tid == 0) atomicAdd(&g_gcnt[cur], run);
            acc = 0.f; run = 0; cur = g;
        }
        acc += __bfloat162float(__ushort_as_bfloat16(h[(size_t)(base + i) * D + tid]));
        run++;
    }
    atomicAdd(&g_gsum[cur * D + tid], acc);
    if (tid == 0) atomicAdd(&g_gcnt[cur], run);
}

// ---------------- head: sigmoid(mean @ fc_w^T + fc_b)
__global__ __launch_bounds__(128) void k_final(const float* __restrict__ fcw,
                                               const float* __restrict__ fcb,
                                               float* __restrict__ out) {
    __shared__ float red[128];
    int g = blockIdx.x;
    int tid = threadIdx.x;
    red[tid] = g_gsum[g * D + tid] * fcw[tid];
    __syncthreads();
#pragma unroll
    for (int s = 64; s > 0; s >>= 1) {
        if (tid < s) red[tid] += red[tid + s];
        __syncthreads();
    }
    if (tid == 0) {
        int c = g_gcnt[g]; if (c < 1) c = 1;
        float x = red[0] / (float)c + fcb[0];
        out[g] = 1.f / (1.f + expf(-x));
    }
}

// ---------------- launch ----------------
extern "C" void kernel_launch(void* const* d_in, const int* in_sizes, int n_in,
                              void* d_out, int out_size) {
    const float* h    = (const float*)d_in[0];
    const int*   src  = (const int*)  d_in[1];
    const int*   dst  = (const int*)  d_in[2];
    const int*   gid  = (const int*)  d_in[3];
    const float* W[5] = {(const float*)d_in[4],  (const float*)d_in[6],
                         (const float*)d_in[8],  (const float*)d_in[10],
                         (const float*)d_in[12]};
    const float* b[5] = {(const float*)d_in[5],  (const float*)d_in[7],
                         (const float*)d_in[9],  (const float*)d_in[11],
                         (const float*)d_in[13]};
    const float* fcw  = (const float*)d_in[14];
    const float* fcb  = (const float*)d_in[15];
    float* out = (float*)d_out;

    cudaFuncSetAttribute(k_gemm, cudaFuncAttributeMaxDynamicSharedMemorySize, GEMM_SMEM);

    unsigned short* Wbt;
    cudaGetSymbolAddress((void**)&Wbt, g_Wbt);

    k_zero<<<256, 256>>>();
    k_deg <<<(N_EDGES / 4 + 255) / 256, 256>>>(src, dst);
    k_norm<<<(N_NODES + 255) / 256, 256>>>();
    k_cvt <<<(N_NODES * 32 + 255) / 256, 256>>>(h);         // needs norm_src
    k_cvtW<<<(5 * D * D + 255) / 256, 256>>>(W[0], W[1], W[2], W[3], W[4]);
    k_fill<<<(N_EDGES / 4 + 255) / 256, 256>>>(src, dst);

    const int spmm_blocks = (N_NODES * 32) / 256;          // 12500
    const int gemm_blocks = (N_NODES + BM - 1) / BM;       // 782

    for (int l = 0; l < 5; l++) {
        k_spmm<<<spmm_blocks, 256>>>();
        k_gemm<<<gemm_blocks, 256, GEMM_SMEM>>>(Wbt + l * D * D, b[l], l < 4 ? 1 : 0);
    }

    k_pool <<<(N_NODES + POOL_NODES - 1) / POOL_NODES, 128>>>(gid);
    k_final<<<N_GRAPHS, 128>>>(fcw, fcb, out);
}

// round 9
// speedup vs baseline: 1.1115x; 1.0045x over previous
#include <cuda_runtime.h>
#include <cuda_bf16.h>
#include <cuda_fp16.h>
#include <cuda_fp8.h>
#include <math.h>

#define N_NODES 100000
#define N_EDGES 1600000
#define N_GRAPHS 64
#define D 128
#define FP8_SCALE 16.0f
#define FP8_INV (1.0f / 16.0f)

// ---------------- scratch (no allocations allowed) ----------------
__device__ uint4 g_bufF8[N_NODES * 8];    // fp8 e4m3 features (x norm_src x 16): SpMM input
__device__ uint4 g_bufB4[N_NODES * 16];   // bf16 agg: SpMM output / GEMM input
__device__ uint4 g_bufA4[N_NODES * 16];   // bf16 final-layer output (pooling input)
__device__ unsigned short g_Wbt[5 * D * D]; // bf16 W transposed: [l][n][k]
__device__ float g_norm_src[N_NODES];
__device__ float g_norm_dst[N_NODES];
__device__ int   g_indeg[N_NODES];
__device__ int   g_outdeg[N_NODES];
__device__ int   g_rowstart[N_NODES];
__device__ int   g_cursor[N_NODES];
__device__ int   g_col[N_EDGES];
__device__ float g_gsum[N_GRAPHS * D];
__device__ int   g_gcnt[N_GRAPHS];
__device__ int   g_ctr;

__device__ __forceinline__ unsigned packbf2(float lo, float hi) {
    __nv_bfloat162 p = __floats2bfloat162_rn(lo, hi);
    return *reinterpret_cast<unsigned*>(&p);
}
__device__ __forceinline__ unsigned short packf8x2(float lo, float hi) {
    return __nv_cvt_float2_to_fp8x2(make_float2(lo, hi), __NV_SATFINITE, __NV_E4M3);
}

// ---------------- init ----------------
__global__ void k_zero() {
    int i = blockIdx.x * blockDim.x + threadIdx.x;
    int stride = gridDim.x * blockDim.x;
    for (int j = i; j < N_NODES; j += stride) {
        g_indeg[j] = 0; g_outdeg[j] = 0; g_cursor[j] = 0;
    }
    for (int j = i; j < N_GRAPHS * D; j += stride) g_gsum[j] = 0.f;
    if (i < N_GRAPHS) g_gcnt[i] = 0;
    if (i == 0) g_ctr = 0;
}

__global__ __launch_bounds__(256) void k_deg(const int* __restrict__ src, const int* __restrict__ dst) {
    int t = blockIdx.x * blockDim.x + threadIdx.x;
    if (t >= N_EDGES / 4) return;
    int4 s = ((const int4*)src)[t];
    int4 d = ((const int4*)dst)[t];
    atomicAdd(&g_outdeg[s.x], 1); atomicAdd(&g_outdeg[s.y], 1);
    atomicAdd(&g_outdeg[s.z], 1); atomicAdd(&g_outdeg[s.w], 1);
    atomicAdd(&g_indeg[d.x], 1);  atomicAdd(&g_indeg[d.y], 1);
    atomicAdd(&g_indeg[d.z], 1);  atomicAdd(&g_indeg[d.w], 1);
}

__global__ void k_norm() {
    int i = blockIdx.x * blockDim.x + threadIdx.x;
    if (i >= N_NODES) return;
    int od = g_outdeg[i], id = g_indeg[i];
    g_norm_src[i] = rsqrtf((float)(od > 1 ? od : 1));
    g_norm_dst[i] = rsqrtf((float)(id > 1 ? id : 1));
    g_rowstart[i] = atomicAdd(&g_ctr, id);
}

// h (fp32) -> fp8 (x norm_src x 16). After k_norm. Thread = 8 features.
__global__ __launch_bounds__(256) void k_cvt(const float* __restrict__ h) {
    int i = blockIdx.x * blockDim.x + threadIdx.x;
    if (i >= N_NODES * 16) return;
    float ns = g_norm_src[i >> 4] * FP8_SCALE;
    float4 v0 = ((const float4*)h)[i * 2];
    float4 v1 = ((const float4*)h)[i * 2 + 1];
    unsigned short p0 = packf8x2(v0.x * ns, v0.y * ns);
    unsigned short p1 = packf8x2(v0.z * ns, v0.w * ns);
    unsigned short p2 = packf8x2(v1.x * ns, v1.y * ns);
    unsigned short p3 = packf8x2(v1.z * ns, v1.w * ns);
    uint2 o;
    o.x = (unsigned)p0 | ((unsigned)p1 << 16);
    o.y = (unsigned)p2 | ((unsigned)p3 << 16);
    ((uint2*)g_bufF8)[i] = o;
}

// all 5 weights fp32 [k][n] -> bf16 transposed [n][k]
__global__ __launch_bounds__(256) void k_cvtW(const float* W0, const float* W1,
                                              const float* W2, const float* W3,
                                              const float* W4) {
    int idx = blockIdx.x * blockDim.x + threadIdx.x;
    if (idx >= 5 * D * D) return;
    const float* Wl[5] = {W0, W1, W2, W3, W4};
    int l = idx >> 14, rem = idx & (D * D - 1);
    int n = rem >> 7, k = rem & 127;
    g_Wbt[idx] = __bfloat16_as_ushort(__float2bfloat16_rn(Wl[l][k * D + n]));
}

__global__ __launch_bounds__(256) void k_fill(const int* __restrict__ src, const int* __restrict__ dst) {
    int t = blockIdx.x * blockDim.x + threadIdx.x;
    if (t >= N_EDGES / 4) return;
    int4 s = ((const int4*)src)[t];
    int4 d = ((const int4*)dst)[t];
    int p0 = atomicAdd(&g_cursor[d.x], 1);
    int p1 = atomicAdd(&g_cursor[d.y], 1);
    int p2 = atomicAdd(&g_cursor[d.z], 1);
    int p3 = atomicAdd(&g_cursor[d.w], 1);
    g_col[g_rowstart[d.x] + p0] = s.x;
    g_col[g_rowstart[d.y] + p1] = s.y;
    g_col[g_rowstart[d.z] + p2] = s.z;
    g_col[g_rowstart[d.w] + p3] = s.w;
}

// ---------------- SpMM (fp8 gather, fp16 accumulate, bf16 out):
// agg[i] = (norm_dst[i]/16) * sum_{e in row i} f8[col[e]]
// Warp per dst node, 4 edges per step: quarter q = lane>>3 handles edge e+q,
// 8 lanes x uint4 (16 fp8 feats) per row. 16-edge unroll = 4 col chains.
__global__ __launch_bounds__(256) void k_spmm() {
    int gt = blockIdx.x * blockDim.x + threadIdx.x;
    int node = gt >> 5;
    int lane = gt & 31;
    if (node >= N_NODES) return;
    int q   = lane >> 3;             // 0..3: edge slot
    int sub = lane & 7;              // uint4 index within 128B row

    const uint4* __restrict__ hb = g_bufF8;
    const int start = g_rowstart[node];
    const int deg   = g_indeg[node];

    // 8 half2 accumulators = 16 features per lane
    unsigned acc[8];
#pragma unroll
    for (int i = 0; i < 8; i++) acc[i] = 0u;

#define ACCW(a0, a1, w) \
    asm("{\n\t" \
        ".reg .b16 lo, hi;\n\t" \
        ".reg .b32 f0, f1;\n\t" \
        "mov.b32 {lo, hi}, %2;\n\t" \
        "cvt.rn.f16x2.e4m3x2 f0, lo;\n\t" \
        "cvt.rn.f16x2.e4m3x2 f1, hi;\n\t" \
        "add.rn.f16x2 %0, %0, f0;\n\t" \
        "add.rn.f16x2 %1, %1, f1;\n\t" \
        "}" : "+r"(a0), "+r"(a1) : "r"(w))
#define ACC16(v) do { \
        ACCW(acc[0], acc[1], (v).x); \
        ACCW(acc[2], acc[3], (v).y); \
        ACCW(acc[4], acc[5], (v).z); \
        ACCW(acc[6], acc[7], (v).w); \
    } while (0)

    int e = 0;
    for (; e + 16 <= deg; e += 16) {          // 4 independent chains
        int cA = g_col[start + e + q];
        int cB = g_col[start + e + 4 + q];
        int cC = g_col[start + e + 8 + q];
        int cD = g_col[start + e + 12 + q];
        uint4 vA = hb[(size_t)cA * 8 + sub];
        uint4 vB = hb[(size_t)cB * 8 + sub];
        uint4 vC = hb[(size_t)cC * 8 + sub];
        uint4 vD = hb[(size_t)cD * 8 + sub];
        ACC16(vA); ACC16(vB); ACC16(vC); ACC16(vD);
    }
    for (; e + 4 <= deg; e += 4) {
        int c = g_col[start + e + q];
        uint4 v = hb[(size_t)c * 8 + sub];
        ACC16(v);
    }
    if (e < deg && q < deg - e) {             // remainder 1..3 edges
        int c = g_col[start + e + q];
        uint4 v = hb[(size_t)c * 8 + sub];
        ACC16(v);
    }
#undef ACC16
#undef ACCW

    // reduce across quarters (lanes L, L^8, L^16, L^24 hold same features)
#pragma unroll
    for (int i = 0; i < 8; i++) {
        unsigned o8 = __shfl_xor_sync(0xffffffffu, acc[i], 8);
        asm("add.rn.f16x2 %0, %0, %1;" : "+r"(acc[i]) : "r"(o8));
        unsigned o16 = __shfl_xor_sync(0xffffffffu, acc[i], 16);
        asm("add.rn.f16x2 %0, %0, %1;" : "+r"(acc[i]) : "r"(o16));
    }

    if (q == 0) {                              // lanes 0..7 write bf16 row
        float nd = g_norm_dst[node] * FP8_INV;
        float2 f[8];
#pragma unroll
        for (int i = 0; i < 8; i++) {
            __half2 h2 = *reinterpret_cast<__half2*>(&acc[i]);
            f[i] = __half22float2(h2);
            f[i].x *= nd; f[i].y *= nd;
        }
        uint4 o0, o1;
        o0.x = packbf2(f[0].x, f[0].y); o0.y = packbf2(f[1].x, f[1].y);
        o0.z = packbf2(f[2].x, f[2].y); o0.w = packbf2(f[3].x, f[3].y);
        o1.x = packbf2(f[4].x, f[4].y); o1.y = packbf2(f[5].x, f[5].y);
        o1.z = packbf2(f[6].x, f[6].y); o1.w = packbf2(f[7].x, f[7].y);
        g_bufB4[(size_t)node * 16 + sub * 2]     = o0;
        g_bufB4[(size_t)node * 16 + sub * 2 + 1] = o1;
    }
}

// ---------------- GEMM (bf16 tensor cores): out = (bufB @ W + b)
// mode 0 (layers 0-3): write fp8 (x norm_src x 16) to g_bufF8
// mode 1 (layer 4):    write bf16 unscaled to g_bufA4
#define BM 128
#define AS_STRIDE 136
#define WS_STRIDE 136
#define WS_ELEMS (D * WS_STRIDE)
#define GEMM_SMEM ((WS_ELEMS + BM * AS_STRIDE) * 2)   // 69632 B

__global__ __launch_bounds__(256, 2) void k_gemm(const unsigned short* __restrict__ Wbt,
                                                 const float* __restrict__ bias,
                                                 int final_layer) {
    extern __shared__ __align__(16) unsigned short sm16[];
    unsigned short* Ws = sm16;               // [n=128][k stride 136]
    unsigned short* As = sm16 + WS_ELEMS;    // [m=128][k stride 136]
    int tid = threadIdx.x;
    int row0 = blockIdx.x * BM;

    const uint4* Wt4 = (const uint4*)Wbt;    // 2048 uint4
#pragma unroll
    for (int i = 0; i < 8; i++) {
        int f = tid + i * 256;
        int n = f >> 4, k0 = (f & 15) * 8;
        *(uint4*)(Ws + n * WS_STRIDE + k0) = Wt4[f];
    }
#pragma unroll
    for (int i = 0; i < 8; i++) {
        int f = tid + i * 256;               // 2048 uint4 (16 per row)
        int r = f >> 4, c = f & 15;
        int grow = row0 + r;
        uint4 v = (grow < N_NODES) ? g_bufB4[(size_t)grow * 16 + c]
                                   : make_uint4(0u, 0u, 0u, 0u);
        *(uint4*)(As + r * AS_STRIDE + c * 8) = v;
    }
    __syncthreads();

    int warp = tid >> 5, lane = tid & 31;
    int wm = (warp >> 2) * 64;
    int wn = (warp & 3) * 32;
    int qr = lane >> 2;
    int qc = lane & 3;

    float c[4][4][4];
#pragma unroll
    for (int mt = 0; mt < 4; mt++)
#pragma unroll
        for (int nt = 0; nt < 4; nt++)
#pragma unroll
            for (int j = 0; j < 4; j++) c[mt][nt][j] = 0.f;

#pragma unroll
    for (int ks = 0; ks < 8; ks++) {
        int k0 = ks * 16;
        unsigned a[4][4];
#pragma unroll
        for (int mt = 0; mt < 4; mt++) {
            const unsigned short* base = As + (wm + mt * 16 + qr) * AS_STRIDE + k0 + 2 * qc;
            a[mt][0] = *(const unsigned*)(base);
            a[mt][1] = *(const unsigned*)(base + 8 * AS_STRIDE);
            a[mt][2] = *(const unsigned*)(base + 8);
            a[mt][3] = *(const unsigned*)(base + 8 * AS_STRIDE + 8);
        }
#pragma unroll
        for (int nt = 0; nt < 4; nt++) {
            const unsigned short* bb = Ws + (wn + nt * 8 + qr) * WS_STRIDE + k0 + 2 * qc;
            unsigned b0 = *(const unsigned*)(bb);
            unsigned b1 = *(const unsigned*)(bb + 8);
#pragma unroll
            for (int mt = 0; mt < 4; mt++) {
                asm volatile(
                    "mma.sync.aligned.m16n8k16.row.col.f32.bf16.bf16.f32 "
                    "{%0,%1,%2,%3}, {%4,%5,%6,%7}, {%8,%9}, {%0,%1,%2,%3};"
                    : "+f"(c[mt][nt][0]), "+f"(c[mt][nt][1]),
                      "+f"(c[mt][nt][2]), "+f"(c[mt][nt][3])
                    : "r"(a[mt][0]), "r"(a[mt][1]), "r"(a[mt][2]), "r"(a[mt][3]),
                      "r"(b0), "r"(b1));
            }
        }
    }

    if (!final_layer) {
        // fp8 out, pre-scaled by norm_src * 16
        unsigned short* outb = (unsigned short*)g_bufF8;  // row stride 64 ushorts
#pragma unroll
        for (int mt = 0; mt < 4; mt++) {
            int r_lo = row0 + wm + mt * 16 + qr;
            int r_hi = r_lo + 8;
            float s_lo = (r_lo < N_NODES) ? g_norm_src[r_lo] * FP8_SCALE : 0.f;
            float s_hi = (r_hi < N_NODES) ? g_norm_src[r_hi] * FP8_SCALE : 0.f;
#pragma unroll
            for (int nt = 0; nt < 4; nt++) {
                int col = wn + nt * 8 + qc * 2;
                float2 bb = *(const float2*)(bias + col);
                if (r_lo < N_NODES)
                    outb[(size_t)r_lo * 64 + (col >> 1)] =
                        packf8x2((c[mt][nt][0] + bb.x) * s_lo, (c[mt][nt][1] + bb.y) * s_lo);
                if (r_hi < N_NODES)
                    outb[(size_t)r_hi * 64 + (col >> 1)] =
                        packf8x2((c[mt][nt][2] + bb.x) * s_hi, (c[mt][nt][3] + bb.y) * s_hi);
            }
        }
    } else {
        // bf16 out, unscaled (pooling input)
        unsigned short* outb = (unsigned short*)g_bufA4;
#pragma unroll
        for (int mt = 0; mt < 4; mt++) {
            int r_lo = row0 + wm + mt * 16 + qr;
            int r_hi = r_lo + 8;
#pragma unroll
            for (int nt = 0; nt < 4; nt++) {
                int col = wn + nt * 8 + qc * 2;
                float2 bb = *(const float2*)(bias + col);
                if (r_lo < N_NODES)
                    *(unsigned*)(outb + (size_t)r_lo * D + col) =
                        packbf2(c[mt][nt][0] + bb.x, c[mt][nt][1] + bb.y);
                if (r_hi < N_NODES)
                    *(unsigned*)(outb + (size_t)r_hi * D + col) =
                        packbf2(c[mt][nt][2] + bb.x, c[mt][nt][3] + bb.y);
            }
        }
    }
}

// ---------------- mean-pool (graph_ids sorted -> run-length segmented reduce)
#define POOL_NODES 256
__global__ __launch_bounds__(128) void k_pool(const int* __restrict__ gid) {
    __shared__ int sg[POOL_NODES];
    int base = blockIdx.x * POOL_NODES;
    int tid = threadIdx.x;   // feature index
    for (int i = tid; i < POOL_NODES; i += 128) {
        int n = base + i;
        sg[i] = (n < N_NODES) ? gid[n] : -1;
    }
    __syncthreads();
    int nn = N_NODES - base; if (nn > POOL_NODES) nn = POOL_NODES;
    const unsigned short* h = (const unsigned short*)g_bufA4;

    float acc = 0.f;
    int cur = sg[0];
    int run = 0;
    for (int i = 0; i < nn; i++) {
        int g = sg[i];
        if (g != cur) {
            atomicAdd(&g_gsum[cur * D + tid], acc);
            if (tid == 0) atomicAdd(&g_gcnt[cur], run);
            acc = 0.f; run = 0; cur = g;
        }
        acc += __bfloat162float(__ushort_as_bfloat16(h[(size_t)(base + i) * D + tid]));
        run++;
    }
    atomicAdd(&g_gsum[cur * D + tid], acc);
    if (tid == 0) atomicAdd(&g_gcnt[cur], run);
}

// ---------------- head: sigmoid(mean @ fc_w^T + fc_b)
__global__ __launch_bounds__(128) void k_final(const float* __restrict__ fcw,
                                               const float* __restrict__ fcb,
                                               float* __restrict__ out) {
    __shared__ float red[128];
    int g = blockIdx.x;
    int tid = threadIdx.x;
    red[tid] = g_gsum[g * D + tid] * fcw[tid];
    __syncthreads();
#pragma unroll
    for (int s = 64; s > 0; s >>= 1) {
        if (tid < s) red[tid] += red[tid + s];
        __syncthreads();
    }
    if (tid == 0) {
        int c = g_gcnt[g]; if (c < 1) c = 1;
        float x = red[0] / (float)c + fcb[0];
        out[g] = 1.f / (1.f + expf(-x));
    }
}

// ---------------- launch ----------------
extern "C" void kernel_launch(void* const* d_in, const int* in_sizes, int n_in,
                              void* d_out, int out_size) {
    const float* h    = (const float*)d_in[0];
    const int*   src  = (const int*)  d_in[1];
    const int*   dst  = (const int*)  d_in[2];
    const int*   gid  = (const int*)  d_in[3];
    const float* W[5] = {(const float*)d_in[4],  (const float*)d_in[6],
                         (const float*)d_in[8],  (const float*)d_in[10],
                         (const float*)d_in[12]};
    const float* b[5] = {(const float*)d_in[5],  (const float*)d_in[7],
                         (const float*)d_in[9],  (const float*)d_in[11],
                         (const float*)d_in[13]};
    const float* fcw  = (const float*)d_in[14];
    const float* fcb  = (const float*)d_in[15];
    float* out = (float*)d_out;

    cudaFuncSetAttribute(k_gemm, cudaFuncAttributeMaxDynamicSharedMemorySize, GEMM_SMEM);

    unsigned short* Wbt;
    cudaGetSymbolAddress((void**)&Wbt, g_Wbt);

    k_zero<<<256, 256>>>();
    k_deg <<<(N_EDGES / 4 + 255) / 256, 256>>>(src, dst);
    k_norm<<<(N_NODES + 255) / 256, 256>>>();
    k_cvt <<<(N_NODES * 16 + 255) / 256, 256>>>(h);         // needs norm_src
    k_cvtW<<<(5 * D * D + 255) / 256, 256>>>(W[0], W[1], W[2], W[3], W[4]);
    k_fill<<<(N_EDGES / 4 + 255) / 256, 256>>>(src, dst);

    const int spmm_blocks = (N_NODES * 32) / 256;          // 12500
    const int gemm_blocks = (N_NODES + BM - 1) / BM;       // 782

    for (int l = 0; l < 5; l++) {
        k_spmm<<<spmm_blocks, 256>>>();
        k_gemm<<<gemm_blocks, 256, GEMM_SMEM>>>(Wbt + l * D * D, b[l], l == 4 ? 1 : 0);
    }

    k_pool <<<(N_NODES + POOL_NODES - 1) / POOL_NODES, 128>>>(gid);
    k_final<<<N_GRAPHS, 128>>>(fcw, fcb, out);
}

// round 10
// speedup vs baseline: 1.1656x; 1.0486x over previous
#include <cuda_runtime.h>
#include <cuda_fp16.h>
#include <math.h>

#define N_NODES 100000
#define N_EDGES 1600000
#define N_GRAPHS 64
#define D 128

// ---------------- scratch (no allocations allowed) ----------------
__device__ uint4 g_bufH16[N_NODES * 16];  // fp16 features (x norm_src): SpMM in / GEMM out
__device__ uint4 g_bufB16[N_NODES * 16];  // fp16 agg: SpMM out / GEMM in
__device__ uint4 g_bufO16[N_NODES * 16];  // fp16 final-layer output (pooling input)
__device__ unsigned short g_Wh[5 * D * D]; // fp16 W transposed: [l][n][k]
__device__ float g_norm_src[N_NODES];
__device__ float g_norm_dst[N_NODES];
__device__ int   g_indeg[N_NODES];
__device__ int   g_outdeg[N_NODES];
__device__ int   g_rowstart[N_NODES];
__device__ int   g_cursor[N_NODES];
__device__ int   g_col[N_EDGES];
__device__ float g_gsum[N_GRAPHS * D];
__device__ int   g_gcnt[N_GRAPHS];
__device__ int   g_ctr;

__device__ __forceinline__ unsigned packh2(float lo, float hi) {
    __half2 p = __floats2half2_rn(lo, hi);
    return *reinterpret_cast<unsigned*>(&p);
}

// ---------------- init ----------------
__global__ void k_zero() {
    int i = blockIdx.x * blockDim.x + threadIdx.x;
    int stride = gridDim.x * blockDim.x;
    for (int j = i; j < N_NODES; j += stride) {
        g_indeg[j] = 0; g_outdeg[j] = 0; g_cursor[j] = 0;
    }
    for (int j = i; j < N_GRAPHS * D; j += stride) g_gsum[j] = 0.f;
    if (i < N_GRAPHS) g_gcnt[i] = 0;
    if (i == 0) g_ctr = 0;
}

__global__ __launch_bounds__(256) void k_deg(const int* __restrict__ src, const int* __restrict__ dst) {
    int t = blockIdx.x * blockDim.x + threadIdx.x;
    if (t >= N_EDGES / 4) return;
    int4 s = ((const int4*)src)[t];
    int4 d = ((const int4*)dst)[t];
    atomicAdd(&g_outdeg[s.x], 1); atomicAdd(&g_outdeg[s.y], 1);
    atomicAdd(&g_outdeg[s.z], 1); atomicAdd(&g_outdeg[s.w], 1);
    atomicAdd(&g_indeg[d.x], 1);  atomicAdd(&g_indeg[d.y], 1);
    atomicAdd(&g_indeg[d.z], 1);  atomicAdd(&g_indeg[d.w], 1);
}

__global__ void k_norm() {
    int i = blockIdx.x * blockDim.x + threadIdx.x;
    if (i >= N_NODES) return;
    int od = g_outdeg[i], id = g_indeg[i];
    g_norm_src[i] = rsqrtf((float)(od > 1 ? od : 1));
    g_norm_dst[i] = rsqrtf((float)(id > 1 ? id : 1));
    g_rowstart[i] = atomicAdd(&g_ctr, id);
}

// h (fp32) -> fp16 (x norm_src). After k_norm. Thread = one float4 -> uint2.
__global__ __launch_bounds__(256) void k_cvt(const float* __restrict__ h) {
    int i = blockIdx.x * blockDim.x + threadIdx.x;
    if (i >= N_NODES * 32) return;
    float ns = g_norm_src[i >> 5];
    float4 v = ((const float4*)h)[i];
    uint2 o;
    o.x = packh2(v.x * ns, v.y * ns);
    o.y = packh2(v.z * ns, v.w * ns);
    ((uint2*)g_bufH16)[i] = o;
}

// all 5 weights fp32 [k][n] -> fp16 transposed [n][k]
__global__ __launch_bounds__(256) void k_cvtW(const float* W0, const float* W1,
                                              const float* W2, const float* W3,
                                              const float* W4) {
    int idx = blockIdx.x * blockDim.x + threadIdx.x;
    if (idx >= 5 * D * D) return;
    const float* Wl[5] = {W0, W1, W2, W3, W4};
    int l = idx >> 14, rem = idx & (D * D - 1);
    int n = rem >> 7, k = rem & 127;
    __half v = __float2half_rn(Wl[l][k * D + n]);
    g_Wh[idx] = *reinterpret_cast<unsigned short*>(&v);
}

__global__ __launch_bounds__(256) void k_fill(const int* __restrict__ src, const int* __restrict__ dst) {
    int t = blockIdx.x * blockDim.x + threadIdx.x;
    if (t >= N_EDGES / 4) return;
    int4 s = ((const int4*)src)[t];
    int4 d = ((const int4*)dst)[t];
    int p0 = atomicAdd(&g_cursor[d.x], 1);
    int p1 = atomicAdd(&g_cursor[d.y], 1);
    int p2 = atomicAdd(&g_cursor[d.z], 1);
    int p3 = atomicAdd(&g_cursor[d.w], 1);
    g_col[g_rowstart[d.x] + p0] = s.x;
    g_col[g_rowstart[d.y] + p1] = s.y;
    g_col[g_rowstart[d.z] + p2] = s.z;
    g_col[g_rowstart[d.w] + p3] = s.w;
}

// ---------------- SpMM (fp16 gather, native HADD2 accumulate, zero converts):
// agg[i] = norm_dst[i] * sum_{e in row i} h16[col[e]]
// Warp per dst node, 2 edges per step (16 lanes x uint4 per 256B row),
// 8-edge unroll = 4 independent col->gather chains. 4 HADD2 per 2 edges.
__global__ __launch_bounds__(256) void k_spmm() {
    int gt = blockIdx.x * blockDim.x + threadIdx.x;
    int node = gt >> 5;
    int lane = gt & 31;
    if (node >= N_NODES) return;
    int eh  = lane >> 4;             // 0/1: which edge of the pair
    int sub = lane & 15;             // uint4 index within 256B row

    const uint4* __restrict__ hb = g_bufH16;
    const int start = g_rowstart[node];
    const int deg   = g_indeg[node];

    unsigned a0 = 0u, a1 = 0u, a2 = 0u, a3 = 0u;   // 4 half2 = 8 features

#define HACC(v) do { \
        asm("add.rn.f16x2 %0, %0, %1;" : "+r"(a0) : "r"((v).x)); \
        asm("add.rn.f16x2 %0, %0, %1;" : "+r"(a1) : "r"((v).y)); \
        asm("add.rn.f16x2 %0, %0, %1;" : "+r"(a2) : "r"((v).z)); \
        asm("add.rn.f16x2 %0, %0, %1;" : "+r"(a3) : "r"((v).w)); \
    } while (0)

    int e = 0;
    for (; e + 8 <= deg; e += 8) {            // 4 independent chains
        int cA = g_col[start + e + eh];
        int cB = g_col[start + e + 2 + eh];
        int cC = g_col[start + e + 4 + eh];
        int cD = g_col[start + e + 6 + eh];
        uint4 vA = hb[(size_t)cA * 16 + sub];
        uint4 vB = hb[(size_t)cB * 16 + sub];
        uint4 vC = hb[(size_t)cC * 16 + sub];
        uint4 vD = hb[(size_t)cD * 16 + sub];
        HACC(vA); HACC(vB); HACC(vC); HACC(vD);
    }
    for (; e + 2 <= deg; e += 2) {
        int c = g_col[start + e + eh];
        uint4 v = hb[(size_t)c * 16 + sub];
        HACC(v);
    }
    if (e < deg && eh == 0) {
        int c = g_col[start + e];
        uint4 v = hb[(size_t)c * 16 + sub];
        HACC(v);
    }
#undef HACC

    // combine halves (lane L <-> L^16 hold the same features)
    unsigned o;
    o = __shfl_xor_sync(0xffffffffu, a0, 16);
    asm("add.rn.f16x2 %0, %0, %1;" : "+r"(a0) : "r"(o));
    o = __shfl_xor_sync(0xffffffffu, a1, 16);
    asm("add.rn.f16x2 %0, %0, %1;" : "+r"(a1) : "r"(o));
    o = __shfl_xor_sync(0xffffffffu, a2, 16);
    asm("add.rn.f16x2 %0, %0, %1;" : "+r"(a2) : "r"(o));
    o = __shfl_xor_sync(0xffffffffu, a3, 16);
    asm("add.rn.f16x2 %0, %0, %1;" : "+r"(a3) : "r"(o));

    if (eh == 0) {
        unsigned nd2 = packh2(g_norm_dst[node], g_norm_dst[node]);
        uint4 w;
        asm("mul.rn.f16x2 %0, %1, %2;" : "=r"(w.x) : "r"(a0), "r"(nd2));
        asm("mul.rn.f16x2 %0, %1, %2;" : "=r"(w.y) : "r"(a1), "r"(nd2));
        asm("mul.rn.f16x2 %0, %1, %2;" : "=r"(w.z) : "r"(a2), "r"(nd2));
        asm("mul.rn.f16x2 %0, %1, %2;" : "=r"(w.w) : "r"(a3), "r"(nd2));
        g_bufB16[(size_t)node * 16 + sub] = w;
    }
}

// ---------------- GEMM (fp16 tensor cores, f32 accum): out = (bufB @ W + b)
// layers 0-3: write fp16 x norm_src to g_bufH16; layer 4: fp16 unscaled to g_bufO16.
#define BM 128
#define AS_STRIDE 136
#define WS_STRIDE 136
#define WS_ELEMS (D * WS_STRIDE)
#define GEMM_SMEM ((WS_ELEMS + BM * AS_STRIDE) * 2)   // 69632 B

__global__ __launch_bounds__(256, 2) void k_gemm(const unsigned short* __restrict__ Wh,
                                                 const float* __restrict__ bias,
                                                 int final_layer) {
    extern __shared__ __align__(16) unsigned short sm16[];
    unsigned short* Ws = sm16;               // [n=128][k stride 136]
    unsigned short* As = sm16 + WS_ELEMS;    // [m=128][k stride 136]
    int tid = threadIdx.x;
    int row0 = blockIdx.x * BM;

    const uint4* Wt4 = (const uint4*)Wh;     // 2048 uint4
#pragma unroll
    for (int i = 0; i < 8; i++) {
        int f = tid + i * 256;
        int n = f >> 4, k0 = (f & 15) * 8;
        *(uint4*)(Ws + n * WS_STRIDE + k0) = Wt4[f];
    }
#pragma unroll
    for (int i = 0; i < 8; i++) {
        int f = tid + i * 256;               // 2048 uint4 (16 per row)
        int r = f >> 4, c = f & 15;
        int grow = row0 + r;
        uint4 v = (grow < N_NODES) ? g_bufB16[(size_t)grow * 16 + c]
                                   : make_uint4(0u, 0u, 0u, 0u);
        *(uint4*)(As + r * AS_STRIDE + c * 8) = v;
    }
    __syncthreads();

    int warp = tid >> 5, lane = tid & 31;
    int wm = (warp >> 2) * 64;
    int wn = (warp & 3) * 32;
    int qr = lane >> 2;
    int qc = lane & 3;

    float c[4][4][4];
#pragma unroll
    for (int mt = 0; mt < 4; mt++)
#pragma unroll
        for (int nt = 0; nt < 4; nt++)
#pragma unroll
            for (int j = 0; j < 4; j++) c[mt][nt][j] = 0.f;

#pragma unroll
    for (int ks = 0; ks < 8; ks++) {
        int k0 = ks * 16;
        unsigned a[4][4];
#pragma unroll
        for (int mt = 0; mt < 4; mt++) {
            const unsigned short* base = As + (wm + mt * 16 + qr) * AS_STRIDE + k0 + 2 * qc;
            a[mt][0] = *(const unsigned*)(base);
            a[mt][1] = *(const unsigned*)(base + 8 * AS_STRIDE);
            a[mt][2] = *(const unsigned*)(base + 8);
            a[mt][3] = *(const unsigned*)(base + 8 * AS_STRIDE + 8);
        }
#pragma unroll
        for (int nt = 0; nt < 4; nt++) {
            const unsigned short* bb = Ws + (wn + nt * 8 + qr) * WS_STRIDE + k0 + 2 * qc;
            unsigned b0 = *(const unsigned*)(bb);
            unsigned b1 = *(const unsigned*)(bb + 8);
#pragma unroll
            for (int mt = 0; mt < 4; mt++) {
                asm volatile(
                    "mma.sync.aligned.m16n8k16.row.col.f32.f16.f16.f32 "
                    "{%0,%1,%2,%3}, {%4,%5,%6,%7}, {%8,%9}, {%0,%1,%2,%3};"
                    : "+f"(c[mt][nt][0]), "+f"(c[mt][nt][1]),
                      "+f"(c[mt][nt][2]), "+f"(c[mt][nt][3])
                    : "r"(a[mt][0]), "r"(a[mt][1]), "r"(a[mt][2]), "r"(a[mt][3]),
                      "r"(b0), "r"(b1));
            }
        }
    }

    unsigned short* outb = final_layer ? (unsigned short*)g_bufO16
                                       : (unsigned short*)g_bufH16;
#pragma unroll
    for (int mt = 0; mt < 4; mt++) {
        int r_lo = row0 + wm + mt * 16 + qr;
        int r_hi = r_lo + 8;
        float s_lo = 1.f, s_hi = 1.f;
        if (!final_layer) {
            s_lo = (r_lo < N_NODES) ? g_norm_src[r_lo] : 0.f;
            s_hi = (r_hi < N_NODES) ? g_norm_src[r_hi] : 0.f;
        }
#pragma unroll
        for (int nt = 0; nt < 4; nt++) {
            int col = wn + nt * 8 + qc * 2;
            float2 bb = *(const float2*)(bias + col);
            if (r_lo < N_NODES)
                *(unsigned*)(outb + (size_t)r_lo * D + col) =
                    packh2((c[mt][nt][0] + bb.x) * s_lo, (c[mt][nt][1] + bb.y) * s_lo);
            if (r_hi < N_NODES)
                *(unsigned*)(outb + (size_t)r_hi * D + col) =
                    packh2((c[mt][nt][2] + bb.x) * s_hi, (c[mt][nt][3] + bb.y) * s_hi);
        }
    }
}

// ---------------- mean-pool (graph_ids sorted -> run-length segmented reduce)
#define POOL_NODES 256
__global__ __launch_bounds__(128) void k_pool(const int* __restrict__ gid) {
    __shared__ int sg[POOL_NODES];
    int base = blockIdx.x * POOL_NODES;
    int tid = threadIdx.x;   // feature index
    for (int i = tid; i < POOL_NODES; i += 128) {
        int n = base + i;
        sg[i] = (n < N_NODES) ? gid[n] : -1;
    }
    __syncthreads();
    int nn = N_NODES - base; if (nn > POOL_NODES) nn = POOL_NODES;
    const unsigned short* h = (const unsigned short*)g_bufO16;

    float acc = 0.f;
    int cur = sg[0];
    int run = 0;
    for (int i = 0; i < nn; i++) {
        int g = sg[i];
        if (g != cur) {
            atomicAdd(&g_gsum[cur * D + tid], acc);
            if (tid == 0) atomicAdd(&g_gcnt[cur], run);
            acc = 0.f; run = 0; cur = g;
        }
        unsigned short u = h[(size_t)(base + i) * D + tid];
        acc += __half2float(*reinterpret_cast<__half*>(&u));
        run++;
    }
    atomicAdd(&g_gsum[cur * D + tid], acc);
    if (tid == 0) atomicAdd(&g_gcnt[cur], run);
}

// ---------------- head: sigmoid(mean @ fc_w^T + fc_b)
__global__ __launch_bounds__(128) void k_final(const float* __restrict__ fcw,
                                               const float* __restrict__ fcb,
                                               float* __restrict__ out) {
    __shared__ float red[128];
    int g = blockIdx.x;
    int tid = threadIdx.x;
    red[tid] = g_gsum[g * D + tid] * fcw[tid];
    __syncthreads();
#pragma unroll
    for (int s = 64; s > 0; s >>= 1) {
        if (tid < s) red[tid] += red[tid + s];
        __syncthreads();
    }
    if (tid == 0) {
        int c = g_gcnt[g]; if (c < 1) c = 1;
        float x = red[0] / (float)c + fcb[0];
        out[g] = 1.f / (1.f + expf(-x));
    }
}

// ---------------- launch ----------------
extern "C" void kernel_launch(void* const* d_in, const int* in_sizes, int n_in,
                              void* d_out, int out_size) {
    const float* h    = (const float*)d_in[0];
    const int*   src  = (const int*)  d_in[1];
    const int*   dst  = (const int*)  d_in[2];
    const int*   gid  = (const int*)  d_in[3];
    const float* W[5] = {(const float*)d_in[4],  (const float*)d_in[6],
                         (const float*)d_in[8],  (const float*)d_in[10],
                         (const float*)d_in[12]};
    const float* b[5] = {(const float*)d_in[5],  (const float*)d_in[7],
                         (const float*)d_in[9],  (const float*)d_in[11],
                         (const float*)d_in[13]};
    const float* fcw  = (const float*)d_in[14];
    const float* fcb  = (const float*)d_in[15];
    float* out = (float*)d_out;

    cudaFuncSetAttribute(k_gemm, cudaFuncAttributeMaxDynamicSharedMemorySize, GEMM_SMEM);

    unsigned short* Wh;
    cudaGetSymbolAddress((void**)&Wh, g_Wh);

    k_zero<<<256, 256>>>();
    k_deg <<<(N_EDGES / 4 + 255) / 256, 256>>>(src, dst);
    k_norm<<<(N_NODES + 255) / 256, 256>>>();
    k_cvt <<<(N_NODES * 32 + 255) / 256, 256>>>(h);         // needs norm_src
    k_cvtW<<<(5 * D * D + 255) / 256, 256>>>(W[0], W[1], W[2], W[3], W[4]);
    k_fill<<<(N_EDGES / 4 + 255) / 256, 256>>>(src, dst);

    const int spmm_blocks = (N_NODES * 32) / 256;          // 12500
    const int gemm_blocks = (N_NODES + BM - 1) / BM;       // 782

    for (int l = 0; l < 5; l++) {
        k_spmm<<<spmm_blocks, 256>>>();
        k_gemm<<<gemm_blocks, 256, GEMM_SMEM>>>(Wh + l * D * D, b[l], l == 4 ? 1 : 0);
    }

    k_pool <<<(N_NODES + POOL_NODES - 1) / POOL_NODES, 128>>>(gid);
    k_final<<<N_GRAPHS, 128>>>(fcw, fcb, out);
}

// round 11
// speedup vs baseline: 1.3385x; 1.1483x over previous
#include <cuda_runtime.h>
#include <cuda_fp16.h>
#include <math.h>

#define N_NODES 100000
#define N_EDGES 1600000
#define N_GRAPHS 64
#define D 128

// ---------------- scratch (no allocations allowed) ----------------
__device__ uint4 g_bufH16[N_NODES * 16];  // fp16 features (x norm_src): SpMM in / GEMM out
__device__ uint4 g_bufB16[N_NODES * 16];  // fp16 agg: SpMM out / GEMM in
__device__ uint4 g_bufO16[N_NODES * 16];  // fp16 final-layer output (pooling input)
__device__ unsigned short g_Wh[5 * D * D]; // fp16 W transposed: [l][n][k]
__device__ float g_norm_src[N_NODES];
__device__ float g_norm_dst[N_NODES];
__device__ int   g_indeg[N_NODES];
__device__ int   g_outdeg[N_NODES];
__device__ int   g_rowstart[N_NODES];
__device__ int   g_cursor[N_NODES];
__device__ int   g_col[N_EDGES];
__device__ float g_gsum[N_GRAPHS * D];
__device__ int   g_gcnt[N_GRAPHS];
__device__ int   g_ctr;

__device__ __forceinline__ unsigned packh2(float lo, float hi) {
    __half2 p = __floats2half2_rn(lo, hi);
    return *reinterpret_cast<unsigned*>(&p);
}

// ---------------- init: zero counters + convert weights (merged) ----------------
__global__ __launch_bounds__(256) void k_init(const float* W0, const float* W1,
                                              const float* W2, const float* W3,
                                              const float* W4) {
    int i = blockIdx.x * blockDim.x + threadIdx.x;
    int stride = gridDim.x * blockDim.x;
    for (int j = i; j < N_NODES; j += stride) {
        g_indeg[j] = 0; g_outdeg[j] = 0; g_cursor[j] = 0;
    }
    for (int j = i; j < N_GRAPHS * D; j += stride) g_gsum[j] = 0.f;
    if (i < N_GRAPHS) g_gcnt[i] = 0;
    if (i == 0) g_ctr = 0;
    // weights fp32 [k][n] -> fp16 transposed [n][k]
    const float* Wl[5] = {W0, W1, W2, W3, W4};
    for (int idx = i; idx < 5 * D * D; idx += stride) {
        int l = idx >> 14, rem = idx & (D * D - 1);
        int n = rem >> 7, k = rem & 127;
        __half v = __float2half_rn(Wl[l][k * D + n]);
        g_Wh[idx] = *reinterpret_cast<unsigned short*>(&v);
    }
}

__global__ __launch_bounds__(256) void k_deg(const int* __restrict__ src, const int* __restrict__ dst) {
    int t = blockIdx.x * blockDim.x + threadIdx.x;
    if (t >= N_EDGES / 4) return;
    int4 s = ((const int4*)src)[t];
    int4 d = ((const int4*)dst)[t];
    atomicAdd(&g_outdeg[s.x], 1); atomicAdd(&g_outdeg[s.y], 1);
    atomicAdd(&g_outdeg[s.z], 1); atomicAdd(&g_outdeg[s.w], 1);
    atomicAdd(&g_indeg[d.x], 1);  atomicAdd(&g_indeg[d.y], 1);
    atomicAdd(&g_indeg[d.z], 1);  atomicAdd(&g_indeg[d.w], 1);
}

// norms + CSR row-start reservation + input convert (merged; cvt computes its
// own rsqrt(outdeg) so it doesn't depend on the norm phase's writes).
__global__ __launch_bounds__(256) void k_norm_cvt(const float* __restrict__ h) {
    int t = blockIdx.x * blockDim.x + threadIdx.x;
    if (t < N_NODES) {
        int od = g_outdeg[t], id = g_indeg[t];
        g_norm_src[t] = rsqrtf((float)(od > 1 ? od : 1));
        g_norm_dst[t] = rsqrtf((float)(id > 1 ? id : 1));
        g_rowstart[t] = atomicAdd(&g_ctr, id);
    }
    if (t < N_NODES * 32) {           // one float4 -> one uint2 (fp16 x norm_src)
        int od = g_outdeg[t >> 5];
        float ns = rsqrtf((float)(od > 1 ? od : 1));
        float4 v = ((const float4*)h)[t];
        uint2 o;
        o.x = packh2(v.x * ns, v.y * ns);
        o.y = packh2(v.z * ns, v.w * ns);
        ((uint2*)g_bufH16)[t] = o;
    }
}

__global__ __launch_bounds__(256) void k_fill(const int* __restrict__ src, const int* __restrict__ dst) {
    int t = blockIdx.x * blockDim.x + threadIdx.x;
    if (t >= N_EDGES / 4) return;
    int4 s = ((const int4*)src)[t];
    int4 d = ((const int4*)dst)[t];
    int p0 = atomicAdd(&g_cursor[d.x], 1);
    int p1 = atomicAdd(&g_cursor[d.y], 1);
    int p2 = atomicAdd(&g_cursor[d.z], 1);
    int p3 = atomicAdd(&g_cursor[d.w], 1);
    g_col[g_rowstart[d.x] + p0] = s.x;
    g_col[g_rowstart[d.y] + p1] = s.y;
    g_col[g_rowstart[d.z] + p2] = s.z;
    g_col[g_rowstart[d.w] + p3] = s.w;
}

// ---------------- SpMM (fp16 gather, native HADD2 accumulate, zero converts):
// agg[i] = norm_dst[i] * sum_{e in row i} h16[col[e]]
// Warp per dst node, 2 edges per step (16 lanes x uint4 per 256B row),
// 8-edge unroll = 4 independent col->gather chains. 4 HADD2 per 2 edges.
__global__ __launch_bounds__(256) void k_spmm() {
    int gt = blockIdx.x * blockDim.x + threadIdx.x;
    int node = gt >> 5;
    int lane = gt & 31;
    if (node >= N_NODES) return;
    int eh  = lane >> 4;             // 0/1: which edge of the pair
    int sub = lane & 15;             // uint4 index within 256B row

    const uint4* __restrict__ hb = g_bufH16;
    const int start = g_rowstart[node];
    const int deg   = g_indeg[node];

    unsigned a0 = 0u, a1 = 0u, a2 = 0u, a3 = 0u;   // 4 half2 = 8 features

#define HACC(v) do { \
        asm("add.rn.f16x2 %0, %0, %1;" : "+r"(a0) : "r"((v).x)); \
        asm("add.rn.f16x2 %0, %0, %1;" : "+r"(a1) : "r"((v).y)); \
        asm("add.rn.f16x2 %0, %0, %1;" : "+r"(a2) : "r"((v).z)); \
        asm("add.rn.f16x2 %0, %0, %1;" : "+r"(a3) : "r"((v).w)); \
    } while (0)

    int e = 0;
    for (; e + 8 <= deg; e += 8) {            // 4 independent chains
        int cA = g_col[start + e + eh];
        int cB = g_col[start + e + 2 + eh];
        int cC = g_col[start + e + 4 + eh];
        int cD = g_col[start + e + 6 + eh];
        uint4 vA = hb[(size_t)cA * 16 + sub];
        uint4 vB = hb[(size_t)cB * 16 + sub];
        uint4 vC = hb[(size_t)cC * 16 + sub];
        uint4 vD = hb[(size_t)cD * 16 + sub];
        HACC(vA); HACC(vB); HACC(vC); HACC(vD);
    }
    for (; e + 2 <= deg; e += 2) {
        int c = g_col[start + e + eh];
        uint4 v = hb[(size_t)c * 16 + sub];
        HACC(v);
    }
    if (e < deg && eh == 0) {
        int c = g_col[start + e];
        uint4 v = hb[(size_t)c * 16 + sub];
        HACC(v);
    }
#undef HACC

    // combine halves (lane L <-> L^16 hold the same features)
    unsigned o;
    o = __shfl_xor_sync(0xffffffffu, a0, 16);
    asm("add.rn.f16x2 %0, %0, %1;" : "+r"(a0) : "r"(o));
    o = __shfl_xor_sync(0xffffffffu, a1, 16);
    asm("add.rn.f16x2 %0, %0, %1;" : "+r"(a1) : "r"(o));
    o = __shfl_xor_sync(0xffffffffu, a2, 16);
    asm("add.rn.f16x2 %0, %0, %1;" : "+r"(a2) : "r"(o));
    o = __shfl_xor_sync(0xffffffffu, a3, 16);
    asm("add.rn.f16x2 %0, %0, %1;" : "+r"(a3) : "r"(o));

    if (eh == 0) {
        unsigned nd2 = packh2(g_norm_dst[node], g_norm_dst[node]);
        uint4 w;
        asm("mul.rn.f16x2 %0, %1, %2;" : "=r"(w.x) : "r"(a0), "r"(nd2));
        asm("mul.rn.f16x2 %0, %1, %2;" : "=r"(w.y) : "r"(a1), "r"(nd2));
        asm("mul.rn.f16x2 %0, %1, %2;" : "=r"(w.z) : "r"(a2), "r"(nd2));
        asm("mul.rn.f16x2 %0, %1, %2;" : "=r"(w.w) : "r"(a3), "r"(nd2));
        g_bufB16[(size_t)node * 16 + sub] = w;
    }
}

// ---------------- GEMM (fp16 tensor cores, f32 accum): out = (bufB @ W + b)
// layers 0-3: write fp16 x norm_src to g_bufH16; layer 4: fp16 unscaled to g_bufO16.
#define BM 128
#define AS_STRIDE 136
#define WS_STRIDE 136
#define WS_ELEMS (D * WS_STRIDE)
#define GEMM_SMEM ((WS_ELEMS + BM * AS_STRIDE) * 2)   // 69632 B

__global__ __launch_bounds__(256, 2) void k_gemm(const unsigned short* __restrict__ Wh,
                                                 const float* __restrict__ bias,
                                                 int final_layer) {
    extern __shared__ __align__(16) unsigned short sm16[];
    unsigned short* Ws = sm16;               // [n=128][k stride 136]
    unsigned short* As = sm16 + WS_ELEMS;    // [m=128][k stride 136]
    int tid = threadIdx.x;
    int row0 = blockIdx.x * BM;

    const uint4* Wt4 = (const uint4*)Wh;     // 2048 uint4
#pragma unroll
    for (int i = 0; i < 8; i++) {
        int f = tid + i * 256;
        int n = f >> 4, k0 = (f & 15) * 8;
        *(uint4*)(Ws + n * WS_STRIDE + k0) = Wt4[f];
    }
#pragma unroll
    for (int i = 0; i < 8; i++) {
        int f = tid + i * 256;               // 2048 uint4 (16 per row)
        int r = f >> 4, c = f & 15;
        int grow = row0 + r;
        uint4 v = (grow < N_NODES) ? g_bufB16[(size_t)grow * 16 + c]
                                   : make_uint4(0u, 0u, 0u, 0u);
        *(uint4*)(As + r * AS_STRIDE + c * 8) = v;
    }
    __syncthreads();

    int warp = tid >> 5, lane = tid & 31;
    int wm = (warp >> 2) * 64;
    int wn = (warp & 3) * 32;
    int qr = lane >> 2;
    int qc = lane & 3;

    float c[4][4][4];
#pragma unroll
    for (int mt = 0; mt < 4; mt++)
#pragma unroll
        for (int nt = 0; nt < 4; nt++)
#pragma unroll
            for (int j = 0; j < 4; j++) c[mt][nt][j] = 0.f;

#pragma unroll
    for (int ks = 0; ks < 8; ks++) {
        int k0 = ks * 16;
        unsigned a[4][4];
#pragma unroll
        for (int mt = 0; mt < 4; mt++) {
            const unsigned short* base = As + (wm + mt * 16 + qr) * AS_STRIDE + k0 + 2 * qc;
            a[mt][0] = *(const unsigned*)(base);
            a[mt][1] = *(const unsigned*)(base + 8 * AS_STRIDE);
            a[mt][2] = *(const unsigned*)(base + 8);
            a[mt][3] = *(const unsigned*)(base + 8 * AS_STRIDE + 8);
        }
#pragma unroll
        for (int nt = 0; nt < 4; nt++) {
            const unsigned short* bb = Ws + (wn + nt * 8 + qr) * WS_STRIDE + k0 + 2 * qc;
            unsigned b0 = *(const unsigned*)(bb);
            unsigned b1 = *(const unsigned*)(bb + 8);
#pragma unroll
            for (int mt = 0; mt < 4; mt++) {
                asm volatile(
                    "mma.sync.aligned.m16n8k16.row.col.f32.f16.f16.f32 "
                    "{%0,%1,%2,%3}, {%4,%5,%6,%7}, {%8,%9}, {%0,%1,%2,%3};"
                    : "+f"(c[mt][nt][0]), "+f"(c[mt][nt][1]),
                      "+f"(c[mt][nt][2]), "+f"(c[mt][nt][3])
                    : "r"(a[mt][0]), "r"(a[mt][1]), "r"(a[mt][2]), "r"(a[mt][3]),
                      "r"(b0), "r"(b1));
            }
        }
    }

    unsigned short* outb = final_layer ? (unsigned short*)g_bufO16
                                       : (unsigned short*)g_bufH16;
#pragma unroll
    for (int mt = 0; mt < 4; mt++) {
        int r_lo = row0 + wm + mt * 16 + qr;
        int r_hi = r_lo + 8;
        float s_lo = 1.f, s_hi = 1.f;
        if (!final_layer) {
            s_lo = (r_lo < N_NODES) ? g_norm_src[r_lo] : 0.f;
            s_hi = (r_hi < N_NODES) ? g_norm_src[r_hi] : 0.f;
        }
#pragma unroll
        for (int nt = 0; nt < 4; nt++) {
            int col = wn + nt * 8 + qc * 2;
            float2 bb = *(const float2*)(bias + col);
            if (r_lo < N_NODES)
                *(unsigned*)(outb + (size_t)r_lo * D + col) =
                    packh2((c[mt][nt][0] + bb.x) * s_lo, (c[mt][nt][1] + bb.y) * s_lo);
            if (r_hi < N_NODES)
                *(unsigned*)(outb + (size_t)r_hi * D + col) =
                    packh2((c[mt][nt][2] + bb.x) * s_hi, (c[mt][nt][3] + bb.y) * s_hi);
        }
    }
}

// ---------------- mean-pool (graph_ids sorted -> run-length segmented reduce)
// 64 nodes/block for better SM parallelism (1563 blocks).
#define POOL_NODES 64
__global__ __launch_bounds__(128) void k_pool(const int* __restrict__ gid) {
    __shared__ int sg[POOL_NODES];
    int base = blockIdx.x * POOL_NODES;
    int tid = threadIdx.x;   // feature index
    for (int i = tid; i < POOL_NODES; i += 128) {
        int n = base + i;
        sg[i] = (n < N_NODES) ? gid[n] : -1;
    }
    __syncthreads();
    int nn = N_NODES - base; if (nn > POOL_NODES) nn = POOL_NODES;
    const unsigned short* h = (const unsigned short*)g_bufO16;

    float acc = 0.f;
    int cur = sg[0];
    int run = 0;
    for (int i = 0; i < nn; i++) {
        int g = sg[i];
        if (g != cur) {
            atomicAdd(&g_gsum[cur * D + tid], acc);
            if (tid == 0) atomicAdd(&g_gcnt[cur], run);
            acc = 0.f; run = 0; cur = g;
        }
        unsigned short u = h[(size_t)(base + i) * D + tid];
        acc += __half2float(*reinterpret_cast<__half*>(&u));
        run++;
    }
    atomicAdd(&g_gsum[cur * D + tid], acc);
    if (tid == 0) atomicAdd(&g_gcnt[cur], run);
}

// ---------------- head: sigmoid(mean @ fc_w^T + fc_b)
__global__ __launch_bounds__(128) void k_final(const float* __restrict__ fcw,
                                               const float* __restrict__ fcb,
                                               float* __restrict__ out) {
    __shared__ float red[128];
    int g = blockIdx.x;
    int tid = threadIdx.x;
    red[tid] = g_gsum[g * D + tid] * fcw[tid];
    __syncthreads();
#pragma unroll
    for (int s = 64; s > 0; s >>= 1) {
        if (tid < s) red[tid] += red[tid + s];
        __syncthreads();
    }
    if (tid == 0) {
        int c = g_gcnt[g]; if (c < 1) c = 1;
        float x = red[0] / (float)c + fcb[0];
        out[g] = 1.f / (1.f + expf(-x));
    }
}

// ---------------- launch ----------------
extern "C" void kernel_launch(void* const* d_in, const int* in_sizes, int n_in,
                              void* d_out, int out_size) {
    const float* h    = (const float*)d_in[0];
    const int*   src  = (const int*)  d_in[1];
    const int*   dst  = (const int*)  d_in[2];
    const int*   gid  = (const int*)  d_in[3];
    const float* W[5] = {(const float*)d_in[4],  (const float*)d_in[6],
                         (const float*)d_in[8],  (const float*)d_in[10],
                         (const float*)d_in[12]};
    const float* b[5] = {(const float*)d_in[5],  (const float*)d_in[7],
                         (const float*)d_in[9],  (const float*)d_in[11],
                         (const float*)d_in[13]};
    const float* fcw  = (const float*)d_in[14];
    const float* fcb  = (const float*)d_in[15];
    float* out = (float*)d_out;

    cudaFuncSetAttribute(k_gemm, cudaFuncAttributeMaxDynamicSharedMemorySize, GEMM_SMEM);

    unsigned short* Wh;
    cudaGetSymbolAddress((void**)&Wh, g_Wh);

    k_init<<<400, 256>>>(W[0], W[1], W[2], W[3], W[4]);
    k_deg <<<(N_EDGES / 4 + 255) / 256, 256>>>(src, dst);
    k_norm_cvt<<<(N_NODES * 32 + 255) / 256, 256>>>(h);
    k_fill<<<(N_EDGES / 4 + 255) / 256, 256>>>(src, dst);

    const int spmm_blocks = (N_NODES * 32) / 256;          // 12500
    const int gemm_blocks = (N_NODES + BM - 1) / BM;       // 782

    for (int l = 0; l < 5; l++) {
        k_spmm<<<spmm_blocks, 256>>>();
        k_gemm<<<gemm_blocks, 256, GEMM_SMEM>>>(Wh + l * D * D, b[l], l == 4 ? 1 : 0);
    }

    k_pool <<<(N_NODES + POOL_NODES - 1) / POOL_NODES, 128>>>(gid);
    k_final<<<N_GRAPHS, 128>>>(fcw, fcb, out);
}